// round 2
// baseline (speedup 1.0000x reference)
#include <cuda_runtime.h>
#include <cuda_bf16.h>

// Upscale_15358803050749: upfirdn2d up=2, 4x4 kernel [1,3,3,1]^2, gain 4.
// x: (8,128,128,128) f32 -> out: (8,128,256,256) f32.
//
// Polyphase (from reference's dilated conv, pad0=2):
//   out[2i]   = K[3]*x[i-1] + K[1]*x[i]
//   out[2i+1] = K[2]*x[i]   + K[0]*x[i+1]      (separably in y and x)
//
// R2: one warp per 8-input-row strip of one plane. Each lane owns 4 input
// cols (float4). Horizontal halos come from __shfl (row width 128 = 32*4,
// lane edges are true image boundary -> zero). Vertical rows roll through
// registers: 8 output-row-pairs cost 10 row loads (amplification 1.25x vs
// 3x in R1).

#define W_IN   128
#define H_IN   128
#define W_OUT  256
#define NC     1024          // 8 * 128 planes
#define STRIPS 16            // H_IN / ROWS_PER_WARP
#define ROWS   8             // input rows per warp

// Load one input row segment into dst[0..5]: dst[1..4] = float4 at ix0,
// dst[0]/dst[5] = halos via warp shuffle (zero at image edge).
__device__ __forceinline__ void load_row(float* dst, const float* rowp,
                                         int ix0, int lane) {
    float4 v = *reinterpret_cast<const float4*>(rowp + ix0);
    dst[1] = v.x; dst[2] = v.y; dst[3] = v.z; dst[4] = v.w;
    float l = __shfl_up_sync(0xffffffffu, v.w, 1);
    float r = __shfl_down_sync(0xffffffffu, v.x, 1);
    dst[0] = (lane == 0)  ? 0.f : l;
    dst[5] = (lane == 31) ? 0.f : r;
}

__device__ __forceinline__ void zero_row(float* dst) {
    #pragma unroll
    for (int i = 0; i < 6; i++) dst[i] = 0.f;
}

__global__ __launch_bounds__(256)
void Upscale_15358803050749_kernel(const float* __restrict__ x,
                                   const float* __restrict__ k,
                                   float* __restrict__ out) {
    int gw    = (blockIdx.x * blockDim.x + threadIdx.x) >> 5;  // global warp
    int lane  = threadIdx.x & 31;
    int strip = gw & (STRIPS - 1);
    int pl    = gw >> 4;                     // plane 0..NC-1
    int iy0   = strip * ROWS;
    int ix0   = lane * 4;

    const float* xp = x   + (size_t)pl * (H_IN * W_IN);
    float*       op = out + (size_t)pl * (256 * W_OUT);

    float K00 = __ldg(k + 0),  K01 = __ldg(k + 1),  K02 = __ldg(k + 2),  K03 = __ldg(k + 3);
    float K10 = __ldg(k + 4),  K11 = __ldg(k + 5),  K12 = __ldg(k + 6),  K13 = __ldg(k + 7);
    float K20 = __ldg(k + 8),  K21 = __ldg(k + 9),  K22 = __ldg(k + 10), K23 = __ldg(k + 11);
    float K30 = __ldg(k + 12), K31 = __ldg(k + 13), K32 = __ldg(k + 14), K33 = __ldg(k + 15);

    // Rolling row registers: a = row(iy-1), b = row(iy), c = row(iy+1).
    float a[6], b[6], c[6];
    if (iy0 > 0) load_row(a, xp + (size_t)(iy0 - 1) * W_IN, ix0, lane);
    else         zero_row(a);
    load_row(b, xp + (size_t)iy0 * W_IN, ix0, lane);

    #pragma unroll
    for (int i = 0; i < ROWS; i++) {
        int iy = iy0 + i;
        if (iy + 1 < H_IN) load_row(c, xp + (size_t)(iy + 1) * W_IN, ix0, lane);
        else               zero_row(c);

        float oe[8], oo[8];
        #pragma unroll
        for (int j = 0; j < 4; j++) {
            int lj = j + 1;
            // out row 2*iy   (even vert phase: K[3]*row(iy-1) + K[1]*row(iy))
            oe[2*j]     = K33 * a[lj-1] + K31 * a[lj]
                        + K13 * b[lj-1] + K11 * b[lj];
            oe[2*j + 1] = K32 * a[lj]   + K30 * a[lj+1]
                        + K12 * b[lj]   + K10 * b[lj+1];
            // out row 2*iy+1 (odd vert phase: K[2]*row(iy) + K[0]*row(iy+1))
            oo[2*j]     = K23 * b[lj-1] + K21 * b[lj]
                        + K03 * c[lj-1] + K01 * c[lj];
            oo[2*j + 1] = K22 * b[lj]   + K20 * b[lj+1]
                        + K02 * c[lj]   + K00 * c[lj+1];
        }

        int ox0 = 2 * ix0;   // multiple of 8 -> aligned float4 stores
        float* oe_p = op + (size_t)(2 * iy) * W_OUT + ox0;
        float* oo_p = op + (size_t)(2 * iy + 1) * W_OUT + ox0;
        *reinterpret_cast<float4*>(oe_p)     = make_float4(oe[0], oe[1], oe[2], oe[3]);
        *reinterpret_cast<float4*>(oe_p + 4) = make_float4(oe[4], oe[5], oe[6], oe[7]);
        *reinterpret_cast<float4*>(oo_p)     = make_float4(oo[0], oo[1], oo[2], oo[3]);
        *reinterpret_cast<float4*>(oo_p + 4) = make_float4(oo[4], oo[5], oo[6], oo[7]);

        // roll rows
        #pragma unroll
        for (int q = 0; q < 6; q++) { a[q] = b[q]; b[q] = c[q]; }
    }
}

extern "C" void kernel_launch(void* const* d_in, const int* in_sizes, int n_in,
                              void* d_out, int out_size) {
    const float* x = (const float*)d_in[0];   // (8,128,128,128)
    const float* k = (const float*)d_in[1];   // (4,4)
    float* out = (float*)d_out;               // (8,128,256,256)

    // warps = NC * STRIPS = 16384 ; threads = 524288 ; blocks = 2048
    int threads = 256;
    int blocks = (NC * STRIPS * 32) / threads;
    Upscale_15358803050749_kernel<<<blocks, threads>>>(x, k, out);
}